// round 3
// baseline (speedup 1.0000x reference)
#include <cuda_runtime.h>
#include <cstdint>
#include <cstddef>

// ---------------------------------------------------------------------------
// GAT layer (sm_103, mma.sync tf32 fallback path — tcgen05 not available on
// this harness's ptxas target).
//   k0 : WT[n][k] = tf32(W[k][n]); reset f2max
//   k0b: wa[2][512] = W^T @ a halves
//   kf : f1 = h@wa1, f2 = h@wa2, f2max (global max, monotone-uint atomicMax)
//   k1 : Wh GEMM (h @ W) -> WhT tf32 [256][8192], mma.sync m16n8k8 tf32
//   k2 : fused masked-exp attention GEMM, fixed softmax bound
//        m_i = lrelu(f1_i + f2max) >= row max; split-j2; P@Wh
//   k3 : combine split partials, divide by l, elu
// ---------------------------------------------------------------------------

static __device__ __forceinline__ uint32_t smem_u32(const void* p) {
    uint32_t a;
    asm("{ .reg .u64 t; cvta.to.shared.u64 t, %1; cvt.u32.u64 %0, t; }" : "=r"(a) : "l"(p));
    return a;
}
static __device__ __forceinline__ uint32_t f32_tf32(float x) {
    uint32_t r; asm("cvt.rna.tf32.f32 %0, %1;" : "=r"(r) : "f"(x)); return r;
}

#define CPA16(dst, src) asm volatile("cp.async.cg.shared.global [%0], [%1], 16;" :: "r"(dst), "l"(src) : "memory")
#define CPA_COMMIT()    asm volatile("cp.async.commit_group;" ::: "memory")
#define CPA_WAIT(n)     asm volatile("cp.async.wait_group %0;" :: "n"(n) : "memory")

static __device__ __forceinline__ void mma8(float* c, const uint32_t* a, const uint32_t* b) {
    asm volatile(
        "mma.sync.aligned.m16n8k8.row.col.f32.tf32.tf32.f32 "
        "{%0,%1,%2,%3},{%4,%5,%6,%7},{%8,%9},{%0,%1,%2,%3};"
        : "+f"(c[0]), "+f"(c[1]), "+f"(c[2]), "+f"(c[3])
        : "r"(a[0]), "r"(a[1]), "r"(a[2]), "r"(a[3]), "r"(b[0]), "r"(b[1]));
}

// monotone float<->uint encoding for atomicMax on floats (handles negatives)
static __device__ __forceinline__ unsigned int enc_f(float f) {
    unsigned int b = __float_as_uint(f);
    return (b & 0x80000000u) ? ~b : (b | 0x80000000u);
}
static __device__ __forceinline__ float dec_f(unsigned int u) {
    return (u & 0x80000000u) ? __uint_as_float(u & 0x7FFFFFFFu) : __uint_as_float(~u);
}

// ------------------------- scratch (device globals) -------------------------
__device__ __align__(16) uint32_t g_WT[256 * 512];    // tf32 W^T [n][k]
__device__ __align__(16) uint32_t g_WhT[256 * 8192];  // tf32 Wh^T [n][i]
__device__ __align__(16) float    g_wa[1024];         // [2][512]
__device__ __align__(16) float    g_f1[8192];
__device__ __align__(16) float    g_f2[8192];
__device__ unsigned int           g_f2max;
__device__ __align__(16) float    g_part[2][8192 * 256];
__device__ __align__(16) float    g_lpart[2][8192];

// ------------------------------- kernel 0 ----------------------------------
__global__ void gat_k0(const float* __restrict__ W) {
    int idx = blockIdx.x * 256 + threadIdx.x;  // 0..131071
    int n = idx >> 9, k = idx & 511;
    g_WT[idx] = f32_tf32(W[k * 256 + n]);
    if (idx == 0) g_f2max = 0u;  // below every real float's encoding
}

// wa[which][k] = sum_n W[k][n] * a[which*256 + n]
__global__ void gat_k0b(const float* __restrict__ W, const float* __restrict__ a) {
    int idx = blockIdx.x * 256 + threadIdx.x;  // 0..1023
    int which = idx >> 9, kk = idx & 511;
    const float* wrow = W + kk * 256;
    const float* ap = a + which * 256;
    float s = 0.f;
    for (int n = 0; n < 256; n++) s += wrow[n] * ap[n];
    g_wa[idx] = s;
}

// f1[i] = h[i,:] . wa1, f2[i] = h[i,:] . wa2, f2max = max(f2)
__global__ void gat_kf(const float* __restrict__ h) {
    __shared__ float swa[1024];
    int tid = threadIdx.x, wid = tid >> 5, lane = tid & 31;
    for (int i = tid; i < 1024; i += 256) swa[i] = g_wa[i];
    __syncthreads();
    int row = blockIdx.x * 8 + wid;
    const float* hr = h + (size_t)row * 512;
    float s1 = 0.f, s2 = 0.f;
    for (int kk = lane; kk < 512; kk += 32) {
        float v = hr[kk];
        s1 += v * swa[kk];
        s2 += v * swa[512 + kk];
    }
#pragma unroll
    for (int o = 16; o > 0; o >>= 1) {
        s1 += __shfl_down_sync(0xFFFFFFFFu, s1, o);
        s2 += __shfl_down_sync(0xFFFFFFFFu, s2, o);
    }
    if (lane == 0) {
        g_f1[row] = s1;
        g_f2[row] = s2;
        atomicMax(&g_f2max, enc_f(s2));
    }
}

// ------------------------------- kernel 1 ----------------------------------
// Wh GEMM: grid 64 (BM=128), BN=256, BK=16, 32 chunks. A = raw h (RZ->tf32),
// B = g_WT (pre-rounded). Double-buffered cp.async, depth-1 prefetch.
// SMEM (floats): As 2*128*20 @0, Bs 2*256*20 @5120  -> 15360 f = 61440 B
__global__ void __launch_bounds__(256, 1) gat_k1(const float* __restrict__ h) {
    extern __shared__ float sm[];
    float* As = sm;
    float* Bs = sm + 5120;

    int tid = threadIdx.x, wid = tid >> 5, lane = tid & 31;
    int wm = wid & 1, wn = wid >> 1;
    int r0 = blockIdx.x * 128;
    int prow = tid >> 1, phalf = tid & 1;

    const float* hrow = h + (size_t)(r0 + prow) * 512 + phalf * 8;
    const uint32_t* bsrc = g_WT + (size_t)tid * 512;

    float c[4][8][4];
#pragma unroll
    for (int mt = 0; mt < 4; mt++)
#pragma unroll
        for (int nt = 0; nt < 8; nt++)
#pragma unroll
            for (int q = 0; q < 4; q++) c[mt][nt][q] = 0.f;

    auto prefetch = [&](int ch) {
        int buf = ch & 1;
        int k0 = ch * 16;
        uint32_t ad = smem_u32(As + buf * 2560 + prow * 20 + phalf * 8);
        CPA16(ad, hrow + k0);
        CPA16(ad + 16, hrow + k0 + 4);
        uint32_t bd = smem_u32(Bs + buf * 5120 + tid * 20);
        const uint32_t* bp = bsrc + k0;
        CPA16(bd, bp); CPA16(bd + 16, bp + 4);
        CPA16(bd + 32, bp + 8); CPA16(bd + 48, bp + 12);
    };

    prefetch(0); CPA_COMMIT();

    for (int ch = 0; ch < 32; ch++) {
        CPA_WAIT(0);
        __syncthreads();
        if (ch + 1 < 32) { prefetch(ch + 1); CPA_COMMIT(); }
        int buf = ch & 1;
        const float* abase = As + buf * 2560 + (wm * 64) * 20;
        const float* bbase = Bs + buf * 5120 + (wn * 64) * 20;
#pragma unroll
        for (int s = 0; s < 2; s++) {
            uint32_t bf[8][2];
#pragma unroll
            for (int nt = 0; nt < 8; nt++) {
                const float* bp = bbase + (nt * 8 + (lane >> 2)) * 20 + s * 8 + (lane & 3);
                bf[nt][0] = *(const uint32_t*)bp;
                bf[nt][1] = *(const uint32_t*)(bp + 4);
            }
#pragma unroll
            for (int mt = 0; mt < 4; mt++) {
                const float* ap = abase + (mt * 16 + (lane >> 2)) * 20 + s * 8 + (lane & 3);
                uint32_t af[4];
                af[0] = *(const uint32_t*)ap;
                af[1] = *(const uint32_t*)(ap + 8 * 20);
                af[2] = *(const uint32_t*)(ap + 4);
                af[3] = *(const uint32_t*)(ap + 8 * 20 + 4);
#pragma unroll
                for (int nt = 0; nt < 8; nt++) mma8(c[mt][nt], af, bf[nt]);
            }
        }
    }

    // epilogue: WhT[n][i] = tf32(c)
#pragma unroll
    for (int mt = 0; mt < 4; mt++) {
        int i = r0 + wm * 64 + mt * 16 + (lane >> 2);
#pragma unroll
        for (int nt = 0; nt < 8; nt++) {
            int n = wn * 64 + nt * 8 + (lane & 3) * 2;
            g_WhT[(size_t)n * 8192 + i]           = f32_tf32(c[mt][nt][0]);
            g_WhT[(size_t)(n + 1) * 8192 + i]     = f32_tf32(c[mt][nt][1]);
            g_WhT[(size_t)n * 8192 + i + 8]       = f32_tf32(c[mt][nt][2]);
            g_WhT[(size_t)(n + 1) * 8192 + i + 8] = f32_tf32(c[mt][nt][3]);
        }
    }
}

// ------------------------------- kernel 2 ----------------------------------
// Fused attention GEMM: grid 128 = 64 rowblocks x split-j2. BM=128, BN=256,
// BK=16, 256 chunks over the 4096-wide j half.
// SMEM (floats): f2s 4096 @0 | As 2*2560 @4096 | Bs 3*5120 @9216 |
//                AdjS(int) 3*2048 @24576   -> 30720 f = 122880 B
__global__ void __launch_bounds__(256, 1) gat_k2(const int* __restrict__ adj) {
    extern __shared__ float sm[];
    float* f2s = sm;
    float* As = sm + 4096;
    float* Bs = sm + 9216;
    int* AdjS = (int*)(sm + 24576);

    int tid = threadIdx.x, wid = tid >> 5, lane = tid & 31;
    int wm = wid & 1, wn = wid >> 1;
    int rb = blockIdx.x & 63, sp = blockIdx.x >> 6;
    int r0 = rb * 128;
    int jbase = sp * 4096;
    int prow = tid >> 1, phalf = tid & 1;

    // stage f2 half-range
    for (int i = tid; i < 4096; i += 256) f2s[i] = g_f2[jbase + i];

    float f2m = dec_f(g_f2max);
    float f1r = g_f1[r0 + prow];
    float tb = f1r + f2m;
    float m_r = fmaxf(tb, 0.2f * tb);  // fixed per-row softmax bound
    float l_acc = 0.f;

    const int* adjrow = adj + (size_t)(r0 + prow) * 8192 + jbase + phalf * 8;
    const uint32_t* bsrc = g_WhT + (size_t)tid * 8192 + jbase;

    float c[4][8][4];
#pragma unroll
    for (int mt = 0; mt < 4; mt++)
#pragma unroll
        for (int nt = 0; nt < 8; nt++)
#pragma unroll
            for (int q = 0; q < 4; q++) c[mt][nt][q] = 0.f;

    auto prefetch = [&](int ch) {
        int b = ch % 3;
        int j0 = ch * 16;
        uint32_t bd = smem_u32(Bs + b * 5120 + tid * 20);
        const uint32_t* bp = bsrc + j0;
        CPA16(bd, bp); CPA16(bd + 16, bp + 4);
        CPA16(bd + 32, bp + 8); CPA16(bd + 48, bp + 12);
        uint32_t ad = smem_u32(AdjS + b * 2048 + prow * 16 + phalf * 8);
        CPA16(ad, adjrow + j0);
        CPA16(ad + 16, adjrow + j0 + 4);
    };

    auto compute = [&](int ch) {  // P(ch) -> As[ch&1]
        int b = ch % 3;
        int j0 = ch * 16;
        const int* ap = AdjS + b * 2048 + prow * 16 + phalf * 8;
        int4 av0 = *(const int4*)ap;
        int4 av1 = *(const int4*)(ap + 4);
        const float* fp = f2s + j0 + phalf * 8;
        float4 fv0 = *(const float4*)fp;
        float4 fv1 = *(const float4*)(fp + 4);
        float p[8];
        float t;
        t = f1r + fv0.x; t = fmaxf(t, 0.2f * t); p[0] = (av0.x > 0) ? __expf(t - m_r) : 0.f;
        t = f1r + fv0.y; t = fmaxf(t, 0.2f * t); p[1] = (av0.y > 0) ? __expf(t - m_r) : 0.f;
        t = f1r + fv0.z; t = fmaxf(t, 0.2f * t); p[2] = (av0.z > 0) ? __expf(t - m_r) : 0.f;
        t = f1r + fv0.w; t = fmaxf(t, 0.2f * t); p[3] = (av0.w > 0) ? __expf(t - m_r) : 0.f;
        t = f1r + fv1.x; t = fmaxf(t, 0.2f * t); p[4] = (av1.x > 0) ? __expf(t - m_r) : 0.f;
        t = f1r + fv1.y; t = fmaxf(t, 0.2f * t); p[5] = (av1.y > 0) ? __expf(t - m_r) : 0.f;
        t = f1r + fv1.z; t = fmaxf(t, 0.2f * t); p[6] = (av1.z > 0) ? __expf(t - m_r) : 0.f;
        t = f1r + fv1.w; t = fmaxf(t, 0.2f * t); p[7] = (av1.w > 0) ? __expf(t - m_r) : 0.f;
        uint4 r0v, r1v;
        r0v.x = f32_tf32(p[0]); r0v.y = f32_tf32(p[1]);
        r0v.z = f32_tf32(p[2]); r0v.w = f32_tf32(p[3]);
        r1v.x = f32_tf32(p[4]); r1v.y = f32_tf32(p[5]);
        r1v.z = f32_tf32(p[6]); r1v.w = f32_tf32(p[7]);
        l_acc += (__uint_as_float(r0v.x) + __uint_as_float(r0v.y)) +
                 (__uint_as_float(r0v.z) + __uint_as_float(r0v.w)) +
                 (__uint_as_float(r1v.x) + __uint_as_float(r1v.y)) +
                 (__uint_as_float(r1v.z) + __uint_as_float(r1v.w));
        float* pd = As + (ch & 1) * 2560 + prow * 20 + phalf * 8;
        *(uint4*)pd = r0v;
        *(uint4*)(pd + 4) = r1v;
    };

    prefetch(0); CPA_COMMIT();
    prefetch(1); CPA_COMMIT();
    CPA_WAIT(1);
    __syncthreads();  // f2s + group 0 ready
    compute(0);

    for (int ch = 0; ch < 256; ch++) {
        __syncthreads();  // P(ch) visible; all warps past mma(ch-1)
        if (ch + 2 < 256) { prefetch(ch + 2); CPA_COMMIT(); }
        CPA_WAIT(1);      // group ch+1 done (Adj/Bs[(ch+1)%3] ready)
        if (ch + 1 < 256) compute(ch + 1);
        // mma on chunk ch
        int bb = ch % 3, ab = ch & 1;
        const float* abase = As + ab * 2560 + (wm * 64) * 20;
        const float* bbase = Bs + bb * 5120 + (wn * 64) * 20;
#pragma unroll
        for (int s = 0; s < 2; s++) {
            uint32_t bf[8][2];
#pragma unroll
            for (int nt = 0; nt < 8; nt++) {
                const float* bp = bbase + (nt * 8 + (lane >> 2)) * 20 + s * 8 + (lane & 3);
                bf[nt][0] = *(const uint32_t*)bp;
                bf[nt][1] = *(const uint32_t*)(bp + 4);
            }
#pragma unroll
            for (int mt = 0; mt < 4; mt++) {
                const float* ap = abase + (mt * 16 + (lane >> 2)) * 20 + s * 8 + (lane & 3);
                uint32_t af[4];
                af[0] = *(const uint32_t*)ap;
                af[1] = *(const uint32_t*)(ap + 8 * 20);
                af[2] = *(const uint32_t*)(ap + 4);
                af[3] = *(const uint32_t*)(ap + 8 * 20 + 4);
#pragma unroll
                for (int nt = 0; nt < 8; nt++) mma8(c[mt][nt], af, bf[nt]);
            }
        }
    }

    float lt = l_acc + __shfl_xor_sync(0xFFFFFFFFu, l_acc, 1);
    if (phalf == 0) g_lpart[sp][r0 + prow] = lt;

    // write partials
#pragma unroll
    for (int mt = 0; mt < 4; mt++) {
        int i = r0 + wm * 64 + mt * 16 + (lane >> 2);
#pragma unroll
        for (int nt = 0; nt < 8; nt++) {
            int n = wn * 64 + nt * 8 + (lane & 3) * 2;
            float2 lo = make_float2(c[mt][nt][0], c[mt][nt][1]);
            float2 hi = make_float2(c[mt][nt][2], c[mt][nt][3]);
            *(float2*)&g_part[sp][(size_t)i * 256 + n] = lo;
            *(float2*)&g_part[sp][(size_t)(i + 8) * 256 + n] = hi;
        }
    }
}

// ------------------------------- kernel 3 ----------------------------------
__global__ void gat_k3(float* __restrict__ out) {
    int i = blockIdx.x;
    int c = threadIdx.x;
    float l = g_lpart[0][i] + g_lpart[1][i];
    float hs = g_part[0][i * 256 + c] + g_part[1][i * 256 + c];
    float v = (l > 0.f) ? (hs / l) : 0.f;
    out[i * 256 + c] = (v > 0.f) ? v : (__expf(v) - 1.f);
}

// ------------------------------- launcher ----------------------------------
extern "C" void kernel_launch(void* const* d_in, const int* in_sizes, int n_in,
                              void* d_out, int out_size) {
    const float* h  = (const float*)d_in[0];   // [8192, 512]
    const int* adj  = (const int*)d_in[1];     // [8192, 8192]
    const float* W  = (const float*)d_in[2];   // [512, 256]
    const float* a  = (const float*)d_in[3];   // [512, 1]
    float* out = (float*)d_out;                // [8192, 256]
    (void)in_sizes; (void)n_in; (void)out_size;

    const int SMEM1 = 61440;
    const int SMEM2 = 122880;
    cudaFuncSetAttribute(gat_k1, cudaFuncAttributeMaxDynamicSharedMemorySize, SMEM1);
    cudaFuncSetAttribute(gat_k2, cudaFuncAttributeMaxDynamicSharedMemorySize, SMEM2);

    gat_k0<<<512, 256>>>(W);
    gat_k0b<<<4, 256>>>(W, a);
    gat_kf<<<1024, 256>>>(h);
    gat_k1<<<64, 256, SMEM1>>>(h);
    gat_k2<<<128, 256, SMEM2>>>(adj);
    gat_k3<<<8192, 256>>>(out);
}

// round 4
// speedup vs baseline: 1.1394x; 1.1394x over previous
#include <cuda_runtime.h>
#include <cstdint>
#include <cstddef>

// ---------------------------------------------------------------------------
// GAT layer (sm_103, mma.sync tf32).  R3: exp() eliminated from the N^2 loop
// via piecewise factorization of exp(leaky_relu(f1_i + f2_j) - m_i):
//   s>=0: u_i * v_j     u = e^{f1+f2max-m},   v  = e^{f2_j-f2max}
//   s<0 : uh_i * vh_j   uh = e^{0.2(f1+f2max)-m}, vh = e^{0.2(f2_j-f2max)}
// predicate s>=0  <=>  v_j >= e^{-f1_i-f2max}. All factors in (0,1].
// Permuted-16 operand layouts -> LDS.128 fragment loads.
// ---------------------------------------------------------------------------

static __device__ __forceinline__ uint32_t smem_u32(const void* p) {
    uint32_t a;
    asm("{ .reg .u64 t; cvta.to.shared.u64 t, %1; cvt.u32.u64 %0, t; }" : "=r"(a) : "l"(p));
    return a;
}
static __device__ __forceinline__ uint32_t f32_tf32(float x) {
    uint32_t r; asm("cvt.rna.tf32.f32 %0, %1;" : "=r"(r) : "f"(x)); return r;
}

#define CPA16(dst, src) asm volatile("cp.async.cg.shared.global [%0], [%1], 16;" :: "r"(dst), "l"(src) : "memory")
#define CPA_COMMIT()    asm volatile("cp.async.commit_group;" ::: "memory")
#define CPA_WAIT(n)     asm volatile("cp.async.wait_group %0;" :: "n"(n) : "memory")

static __device__ __forceinline__ void mma8(float* c, const uint32_t* a, const uint32_t* b) {
    asm volatile(
        "mma.sync.aligned.m16n8k8.row.col.f32.tf32.tf32.f32 "
        "{%0,%1,%2,%3},{%4,%5,%6,%7},{%8,%9},{%0,%1,%2,%3};"
        : "+f"(c[0]), "+f"(c[1]), "+f"(c[2]), "+f"(c[3])
        : "r"(a[0]), "r"(a[1]), "r"(a[2]), "r"(a[3]), "r"(b[0]), "r"(b[1]));
}

// monotone float<->uint encoding for atomicMax on floats
static __device__ __forceinline__ unsigned int enc_f(float f) {
    unsigned int b = __float_as_uint(f);
    return (b & 0x80000000u) ? ~b : (b | 0x80000000u);
}
static __device__ __forceinline__ float dec_f(unsigned int u) {
    return (u & 0x80000000u) ? __uint_as_float(u & 0x7FFFFFFFu) : __uint_as_float(~u);
}

// permuted-16 index: within each 16-block, element k stored at (k&3)*4 + (k>>2)
static __device__ __forceinline__ int perm16(int i) {
    return (i & ~15) + ((i & 3) << 2) + ((i >> 2) & 3);
}

// ------------------------- scratch (device globals) -------------------------
__device__ __align__(16) uint32_t g_WT2[256 * 512];    // tf32 W^T, perm16 over k
__device__ __align__(16) uint32_t g_WhT2[256 * 8192];  // tf32 Wh^T, perm16 over i
__device__ __align__(16) float    g_wa[1024];          // [2][512]
__device__ __align__(16) float    g_f1[8192];
__device__ __align__(16) float    g_f2[8192];
__device__ unsigned int           g_f2max;
__device__ __align__(16) float2   g_v[8192];           // (v_j, vh_j)
__device__ __align__(16) float    g_part[2][8192 * 256];
__device__ __align__(16) float    g_lpart[2][8192];

// ------------------------------- kernel 0 ----------------------------------
__global__ void gat_k0(const float* __restrict__ W) {
    int idx = blockIdx.x * 256 + threadIdx.x;  // 0..131071
    int n = idx >> 9, k = idx & 511;
    g_WT2[n * 512 + perm16(k)] = f32_tf32(W[k * 256 + n]);
    if (idx == 0) g_f2max = 0u;
}

// wa[which][k] = sum_n W[k][n] * a[which*256 + n]
__global__ void gat_k0b(const float* __restrict__ W, const float* __restrict__ a) {
    int idx = blockIdx.x * 256 + threadIdx.x;  // 0..1023
    int which = idx >> 9, kk = idx & 511;
    const float* wrow = W + kk * 256;
    const float* ap = a + which * 256;
    float s = 0.f;
    for (int n = 0; n < 256; n++) s += wrow[n] * ap[n];
    g_wa[idx] = s;
}

// f1[i] = h[i,:].wa1, f2[i] = h[i,:].wa2, f2max
__global__ void gat_kf(const float* __restrict__ h) {
    __shared__ float swa[1024];
    int tid = threadIdx.x, wid = tid >> 5, lane = tid & 31;
    for (int i = tid; i < 1024; i += 256) swa[i] = g_wa[i];
    __syncthreads();
    int row = blockIdx.x * 8 + wid;
    const float* hr = h + (size_t)row * 512;
    float s1 = 0.f, s2 = 0.f;
    for (int kk = lane; kk < 512; kk += 32) {
        float v = hr[kk];
        s1 += v * swa[kk];
        s2 += v * swa[512 + kk];
    }
#pragma unroll
    for (int o = 16; o > 0; o >>= 1) {
        s1 += __shfl_down_sync(0xFFFFFFFFu, s1, o);
        s2 += __shfl_down_sync(0xFFFFFFFFu, s2, o);
    }
    if (lane == 0) {
        g_f1[row] = s1;
        g_f2[row] = s2;
        atomicMax(&g_f2max, enc_f(s2));
    }
}

// v_j = e^{f2_j - f2max}, vh_j = e^{0.2(f2_j - f2max)}
__global__ void gat_kv() {
    int j = blockIdx.x * 256 + threadIdx.x;
    float d = g_f2[j] - dec_f(g_f2max);
    g_v[j] = make_float2(__expf(d), __expf(0.2f * d));
}

// ------------------------------- kernel 1 ----------------------------------
// Wh GEMM: grid 128 (BM=64), BN=256, BK=16, 32 chunks, depth-2 cp.async.
// SMEM floats: As 3*64*20=3840 @0 | Bs 3*4096 @3840  -> 16128 f = 64512 B
__global__ void __launch_bounds__(256, 1) gat_k1(const float* __restrict__ h) {
    extern __shared__ float sm[];
    float* As = sm;
    float* Bs = sm + 3840;

    int tid = threadIdx.x, wid = tid >> 5, lane = tid & 31;
    int wm = wid & 1, wn = wid >> 1;
    int r0 = blockIdx.x * 64;
    int arow = tid >> 2, aq = tid & 3;
    const float* hsrc = h + (size_t)(r0 + arow) * 512 + aq * 4;
    const uint32_t* bsrc = g_WT2 + (size_t)tid * 512;

    float c[2][8][4];
#pragma unroll
    for (int mt = 0; mt < 2; mt++)
#pragma unroll
        for (int nt = 0; nt < 8; nt++)
#pragma unroll
            for (int q = 0; q < 4; q++) c[mt][nt][q] = 0.f;

    auto prefetch = [&](int ch) {
        int b = ch % 3, k0c = ch * 16;
        CPA16(smem_u32(As + b * 1280 + arow * 20 + aq * 4), hsrc + k0c);
        uint32_t bd = smem_u32(Bs + b * 4096 + tid * 16);
        const uint32_t* bp = bsrc + k0c;
        CPA16(bd, bp); CPA16(bd + 16, bp + 4);
        CPA16(bd + 32, bp + 8); CPA16(bd + 48, bp + 12);
    };

    prefetch(0); CPA_COMMIT();
    prefetch(1); CPA_COMMIT();
    CPA_WAIT(1);

    for (int ch = 0; ch < 32; ch++) {
        __syncthreads();
        if (ch + 2 < 32) { prefetch(ch + 2); CPA_COMMIT(); CPA_WAIT(1); }
        else CPA_WAIT(0);
        int b = ch % 3;
        const float4* Bb = (const float4*)(Bs + b * 4096);
        const float* Ab = As + b * 1280;
        float4 bv[8];
#pragma unroll
        for (int nt = 0; nt < 8; nt++)
            bv[nt] = Bb[(wn * 64 + nt * 8 + (lane >> 2)) * 4 + (lane & 3)];
#pragma unroll
        for (int mt = 0; mt < 2; mt++) {
            int rl = wm * 32 + mt * 16 + (lane >> 2);
            int cc = lane & 3;
#pragma unroll
            for (int s = 0; s < 2; s++) {
                uint32_t af[4];
                af[0] = *(const uint32_t*)(Ab + rl * 20 + s * 8 + cc);
                af[1] = *(const uint32_t*)(Ab + (rl + 8) * 20 + s * 8 + cc);
                af[2] = *(const uint32_t*)(Ab + rl * 20 + s * 8 + cc + 4);
                af[3] = *(const uint32_t*)(Ab + (rl + 8) * 20 + s * 8 + cc + 4);
#pragma unroll
                for (int nt = 0; nt < 8; nt++) {
                    uint32_t bf[2];
                    if (s == 0) { bf[0] = __float_as_uint(bv[nt].x); bf[1] = __float_as_uint(bv[nt].y); }
                    else        { bf[0] = __float_as_uint(bv[nt].z); bf[1] = __float_as_uint(bv[nt].w); }
                    mma8(c[mt][nt], af, bf);
                }
            }
        }
    }

    // epilogue: WhT2[n][perm16(i)] = tf32(c)
#pragma unroll
    for (int mt = 0; mt < 2; mt++) {
        int i = r0 + wm * 32 + mt * 16 + (lane >> 2);
#pragma unroll
        for (int nt = 0; nt < 8; nt++) {
            int n = wn * 64 + nt * 8 + (lane & 3) * 2;
            g_WhT2[(size_t)n * 8192 + perm16(i)]           = f32_tf32(c[mt][nt][0]);
            g_WhT2[(size_t)(n + 1) * 8192 + perm16(i)]     = f32_tf32(c[mt][nt][1]);
            g_WhT2[(size_t)n * 8192 + perm16(i + 8)]       = f32_tf32(c[mt][nt][2]);
            g_WhT2[(size_t)(n + 1) * 8192 + perm16(i + 8)] = f32_tf32(c[mt][nt][3]);
        }
    }
}

// ------------------------------- kernel 2 ----------------------------------
// Fused attention GEMM: grid 128 = 64 rowblocks x split-j2. BM=128, BN=256,
// BK=16, 256 chunks. No exp in the loop.
// SMEM floats: Vs(float2) 8192 @0 | A2 2*2048 @8192 | B2 3*4096 @12288 |
//              AdjS(int) 3*2048 @24576 -> 30720 f = 122880 B
__global__ void __launch_bounds__(256, 1) gat_k2(const int* __restrict__ adj) {
    extern __shared__ float sm[];
    float2* Vs = (float2*)sm;            // [4096]
    float* A2 = sm + 8192;               // [2][2048]
    float* B2 = sm + 12288;              // [3][4096]
    int* AdjS = (int*)(sm + 24576);      // [3][2048]

    int tid = threadIdx.x, wid = tid >> 5, lane = tid & 31;
    int wm = wid & 1, wn = wid >> 1;
    int rb = blockIdx.x & 63, sp = blockIdx.x >> 6;
    int r0 = rb * 128;
    int jbase = sp * 4096;
    int prow = tid >> 1, ph = tid & 1, c0 = ph * 2;

    // stage (v, vh) pairs for this j-half
    for (int i = tid; i < 4096; i += 256) Vs[i] = g_v[jbase + i];

    float f2m = dec_f(g_f2max);
    float f1r = g_f1[r0 + prow];
    float tb = f1r + f2m;
    float m_r = fmaxf(tb, 0.2f * tb);
    float u   = __expf(tb - m_r);
    float uh  = __expf(0.2f * tb - m_r);
    float thr = __expf(-tb);   // v_j >= thr  <=>  f1r + f2_j >= 0
    float l_acc = 0.f;

    const int* adjrow = adj + (size_t)(r0 + prow) * 8192 + jbase + ph * 8;
    const uint32_t* bsrc = g_WhT2 + (size_t)tid * 8192 + jbase;

    float c[4][8][4];
#pragma unroll
    for (int mt = 0; mt < 4; mt++)
#pragma unroll
        for (int nt = 0; nt < 8; nt++)
#pragma unroll
            for (int q = 0; q < 4; q++) c[mt][nt][q] = 0.f;

    auto prefetch = [&](int ch) {
        int b = ch % 3, j0 = ch * 16;
        uint32_t bd = smem_u32(B2 + b * 4096 + tid * 16);
        const uint32_t* bp = bsrc + j0;
        CPA16(bd, bp); CPA16(bd + 16, bp + 4);
        CPA16(bd + 32, bp + 8); CPA16(bd + 48, bp + 12);
        uint32_t ad = smem_u32(AdjS + b * 2048 + prow * 16 + ph * 8);
        CPA16(ad, adjrow + j0);
        CPA16(ad + 16, adjrow + j0 + 4);
    };

    auto compute = [&](int ch) {  // P(ch) -> A2[ch&1], fragment-permuted
        int b = ch % 3;
        const int* ar = AdjS + b * 2048 + prow * 16;
        const float2* vs = Vs + ch * 16;
        float* dst = A2 + (ch & 1) * 2048 + prow * 16;
#pragma unroll
        for (int t = 0; t < 2; t++) {
            int cc = c0 + t;
            float pv[4];
#pragma unroll
            for (int kq = 0; kq < 4; kq++) {
                int j = cc + kq * 4;
                float2 v2 = vs[j];
                int av = ar[j];
                float sv = (v2.x >= thr) ? v2.x : v2.y;
                float su = (v2.x >= thr) ? u : uh;
                float p = (av > 0) ? su * sv : 0.f;
                p = __uint_as_float(f32_tf32(p));
                l_acc += p;
                pv[kq] = p;
            }
            *(float4*)(dst + cc * 4) = make_float4(pv[0], pv[1], pv[2], pv[3]);
        }
    };

    prefetch(0); CPA_COMMIT();
    prefetch(1); CPA_COMMIT();
    CPA_WAIT(1);
    __syncthreads();
    compute(0);

    for (int ch = 0; ch < 256; ch++) {
        __syncthreads();  // publishes A2[ch&1], group arrivals; joins mma(ch-1)
        if (ch + 2 < 256) { prefetch(ch + 2); CPA_COMMIT(); CPA_WAIT(1); }
        else CPA_WAIT(0);
        if (ch + 1 < 256) compute(ch + 1);

        int b = ch % 3, ab = ch & 1;
        const float4* Bb = (const float4*)(B2 + b * 4096);
        const float4* Aa = (const float4*)(A2 + ab * 2048);
        float4 bv[8];
#pragma unroll
        for (int nt = 0; nt < 8; nt++)
            bv[nt] = Bb[(wn * 64 + nt * 8 + (lane >> 2)) * 4 + (lane & 3)];
#pragma unroll
        for (int mt = 0; mt < 4; mt++) {
            int rl = wm * 64 + mt * 16 + (lane >> 2);
            float4 lo = Aa[rl * 4 + (lane & 3)];
            float4 hi = Aa[(rl + 8) * 4 + (lane & 3)];
            uint32_t a0[4] = {__float_as_uint(lo.x), __float_as_uint(hi.x),
                              __float_as_uint(lo.y), __float_as_uint(hi.y)};
            uint32_t a1[4] = {__float_as_uint(lo.z), __float_as_uint(hi.z),
                              __float_as_uint(lo.w), __float_as_uint(hi.w)};
#pragma unroll
            for (int nt = 0; nt < 8; nt++) {
                uint32_t b0[2] = {__float_as_uint(bv[nt].x), __float_as_uint(bv[nt].y)};
                mma8(c[mt][nt], a0, b0);
                uint32_t b1[2] = {__float_as_uint(bv[nt].z), __float_as_uint(bv[nt].w)};
                mma8(c[mt][nt], a1, b1);
            }
        }
    }

    float lt = l_acc + __shfl_xor_sync(0xFFFFFFFFu, l_acc, 1);
    if (ph == 0) g_lpart[sp][r0 + prow] = lt;

#pragma unroll
    for (int mt = 0; mt < 4; mt++) {
        int i = r0 + wm * 64 + mt * 16 + (lane >> 2);
#pragma unroll
        for (int nt = 0; nt < 8; nt++) {
            int n = wn * 64 + nt * 8 + (lane & 3) * 2;
            float2 lo = make_float2(c[mt][nt][0], c[mt][nt][1]);
            float2 hi = make_float2(c[mt][nt][2], c[mt][nt][3]);
            *(float2*)&g_part[sp][(size_t)i * 256 + n] = lo;
            *(float2*)&g_part[sp][(size_t)(i + 8) * 256 + n] = hi;
        }
    }
}

// ------------------------------- kernel 3 ----------------------------------
__global__ void gat_k3(float* __restrict__ out) {
    int i = blockIdx.x;
    int c = threadIdx.x;
    float l = g_lpart[0][i] + g_lpart[1][i];
    float hs = g_part[0][i * 256 + c] + g_part[1][i * 256 + c];
    float v = (l > 0.f) ? (hs / l) : 0.f;
    out[i * 256 + c] = (v > 0.f) ? v : (__expf(v) - 1.f);
}

// ------------------------------- launcher ----------------------------------
extern "C" void kernel_launch(void* const* d_in, const int* in_sizes, int n_in,
                              void* d_out, int out_size) {
    const float* h  = (const float*)d_in[0];   // [8192, 512]
    const int* adj  = (const int*)d_in[1];     // [8192, 8192]
    const float* W  = (const float*)d_in[2];   // [512, 256]
    const float* a  = (const float*)d_in[3];   // [512, 1]
    float* out = (float*)d_out;                // [8192, 256]
    (void)in_sizes; (void)n_in; (void)out_size;

    const int SMEM1 = 64512;
    const int SMEM2 = 122880;
    cudaFuncSetAttribute(gat_k1, cudaFuncAttributeMaxDynamicSharedMemorySize, SMEM1);
    cudaFuncSetAttribute(gat_k2, cudaFuncAttributeMaxDynamicSharedMemorySize, SMEM2);

    gat_k0<<<512, 256>>>(W);
    gat_k0b<<<4, 256>>>(W, a);
    gat_kf<<<1024, 256>>>(h);
    gat_kv<<<32, 256>>>();
    gat_k1<<<128, 256, SMEM1>>>(h);
    gat_k2<<<128, 256, SMEM2>>>(adj);
    gat_k3<<<8192, 256>>>(out);
}